// round 1
// baseline (speedup 1.0000x reference)
#include <cuda_runtime.h>

// ---------------------------------------------------------------------------
// Model_38225208935040: multi-region perturbed PINN forward.
//
// Key algebraic collapse: for each perturbation grid (linspace symmetric
// around 0), mean_p wave(base + delta_p) = Cd * wave(base), where
//   Cd_j = prod_d [ (1/s) * sum_i cos(lin_i * W1[d, j]) ]
// (mean of sin over a symmetric grid is exactly zero; the grid mean of
// exp(i*sum) factorizes into a product of real per-dimension means).
// So the 496 embedding evaluations per point reduce to ONE wave(base)
// plus elementwise scaling by three precomputed 64-vectors.
// ---------------------------------------------------------------------------

#define PPB 4          // points per block
#define NTHREADS 256

__device__ float g_Cd[3 * 64];   // Cd for regions 1..3 (region 0 == 1.0)

// -------------------------- setup: compute Cd ------------------------------
__global__ void setup_cd_kernel(const float* __restrict__ W1) {
    int tid = threadIdx.x;
    if (tid >= 192) return;
    int r = tid >> 6;        // 0..2 -> perturbation regions 1..3
    int j = tid & 63;        // feature
    const int   S[3] = {3, 5, 7};
    const float R[3] = {0.01f, 0.05f, 0.09f};
    int s = S[r];
    float rr = R[r];
    float inv = 1.0f / (float)s;
    float step = 2.0f * rr / (float)(s - 1);
    float prod = 1.0f;
    #pragma unroll
    for (int d = 0; d < 3; d++) {
        float w = W1[d * 64 + j];
        float c = 0.0f;
        for (int i = 0; i < s; i++) {
            float lin = -rr + step * (float)i;
            c += cosf(lin * w);
        }
        prod *= c * inv;
    }
    g_Cd[r * 64 + j] = prod;
}

// -------------------------- main fused kernel ------------------------------
__global__ void __launch_bounds__(NTHREADS) model_main_kernel(
    const float* __restrict__ x, const float* __restrict__ y, const float* __restrict__ t,
    const float* __restrict__ W1, const float* __restrict__ b1,
    const float* __restrict__ pwa, const float* __restrict__ pwb,
    const float* __restrict__ W2, const float* __restrict__ b2,
    const float* __restrict__ mW1, const float* __restrict__ mb1,
    const float* __restrict__ pmwa, const float* __restrict__ pmwb,
    const float* __restrict__ mW2, const float* __restrict__ pmb2,
    const float* __restrict__ W0, const float* __restrict__ b0,
    const float* __restrict__ pwa0, const float* __restrict__ pwb0,
    const float* __restrict__ Wh, const float* __restrict__ bh,
    const float* __restrict__ wah, const float* __restrict__ wbh,
    const float* __restrict__ Wf1, const float* __restrict__ bf1,
    const float* __restrict__ pwaf, const float* __restrict__ pwbf,
    const float* __restrict__ Wf2, const float* __restrict__ bf2,
    float* __restrict__ out, int npts)
{
    __shared__ float4 swc[PPB][64];     // (w, Cd1*w, Cd2*w, Cd3*w) per feature
    __shared__ float  esh[PPB][256];    // mixed features e
    __shared__ float  hsh[PPB][64];     // out-MLP hidden state

    const int tid = threadIdx.x;
    const int base_pt = blockIdx.x * PPB;

    // ---------------- Phase A: base embedding pre-activation ---------------
    {
        const float wa = pwa[0], wb = pwb[0];
        int pt = tid >> 6;
        int j  = tid & 63;
        int n  = base_pt + pt;
        if (n >= npts) n = npts - 1;               // harmless clamp
        float xv = x[n], yv = y[n], tv = t[n];
        float z = fmaf(xv, W1[j], fmaf(yv, W1[64 + j], fmaf(tv, W1[128 + j], b1[j])));
        float sn, cn;
        __sincosf(z, &sn, &cn);
        float w = fmaf(wa, sn, wb * cn);
        float c1 = g_Cd[j], c2 = g_Cd[64 + j], c3 = g_Cd[128 + j];
        swc[pt][j] = make_float4(w, c1 * w, c2 * w, c3 * w);
    }
    __syncthreads();

    // ---------------- Phase B: 4-region GEMV vs W2 [64,256] ----------------
    // Thread k owns output column k for all PPB points and all 4 regions.
    float acc[PPB][4];
    #pragma unroll
    for (int p = 0; p < PPB; p++)
        #pragma unroll
        for (int r = 0; r < 4; r++)
            acc[p][r] = 0.0f;

    #pragma unroll 4
    for (int j = 0; j < 64; j++) {
        float Wv = W2[j * 256 + tid];
        #pragma unroll
        for (int p = 0; p < PPB; p++) {
            float4 c = swc[p][j];
            acc[p][0] = fmaf(c.x, Wv, acc[p][0]);
            acc[p][1] = fmaf(c.y, Wv, acc[p][1]);
            acc[p][2] = fmaf(c.z, Wv, acc[p][2]);
            acc[p][3] = fmaf(c.w, Wv, acc[p][3]);
        }
    }

    // ---------------- Phase C: multiregion mixer (4 -> 8 -> 1) -------------
    {
        const float b2k = b2[tid];
        const float mwa = pmwa[0], mwb = pmwb[0], mb2v = pmb2[0];
        // small weights: let the compiler hoist into registers
        float m1[32], m1b[8], m2[8];
        #pragma unroll
        for (int i = 0; i < 32; i++) m1[i] = mW1[i];
        #pragma unroll
        for (int h = 0; h < 8; h++) { m1b[h] = mb1[h]; m2[h] = mW2[h]; }

        #pragma unroll
        for (int p = 0; p < PPB; p++) {
            float s0 = acc[p][0] + b2k;
            float s1 = acc[p][1] + b2k;
            float s2 = acc[p][2] + b2k;
            float s3 = acc[p][3] + b2k;
            float ev = mb2v;
            #pragma unroll
            for (int h = 0; h < 8; h++) {
                float z = fmaf(s0, m1[h],
                          fmaf(s1, m1[8 + h],
                          fmaf(s2, m1[16 + h],
                          fmaf(s3, m1[24 + h], m1b[h]))));
                float sn, cn;
                __sincosf(z, &sn, &cn);
                ev = fmaf(fmaf(mwa, sn, mwb * cn), m2[h], ev);
            }
            esh[p][tid] = ev;
        }
    }
    __syncthreads();

    // ---------------- Phase D: out MLP 256->64, 3x(64->64), 64->64, 64->3 --
    const int pt = tid >> 6;
    const int f  = tid & 63;

    // layer 0: 256 -> 64
    {
        float a = b0[f];
        #pragma unroll 4
        for (int k = 0; k < 256; k++)
            a = fmaf(esh[pt][k], W0[k * 64 + f], a);
        float sn, cn;
        __sincosf(a, &sn, &cn);
        hsh[pt][f] = fmaf(pwa0[0], sn, pwb0[0] * cn);
    }
    __syncthreads();

    // 3 hidden layers: 64 -> 64
    for (int L = 0; L < 3; L++) {
        const float* Wl = Wh + L * 64 * 64;
        float a = bh[L * 64 + f];
        #pragma unroll 4
        for (int g = 0; g < 64; g++)
            a = fmaf(hsh[pt][g], Wl[g * 64 + f], a);
        float sn, cn;
        __sincosf(a, &sn, &cn);
        float hv = fmaf(wah[L], sn, wbh[L] * cn);
        __syncthreads();
        hsh[pt][f] = hv;
        __syncthreads();
    }

    // final hidden: 64 -> 64 with wave
    {
        float a = bf1[f];
        #pragma unroll 4
        for (int g = 0; g < 64; g++)
            a = fmaf(hsh[pt][g], Wf1[g * 64 + f], a);
        float sn, cn;
        __sincosf(a, &sn, &cn);
        float hv = fmaf(pwaf[0], sn, pwbf[0] * cn);
        __syncthreads();
        hsh[pt][f] = hv;
        __syncthreads();
    }

    // output: 64 -> 3
    if (f < 3) {
        int n = base_pt + pt;
        if (n < npts) {
            float a = bf2[f];
            #pragma unroll 4
            for (int g = 0; g < 64; g++)
                a = fmaf(hsh[pt][g], Wf2[g * 3 + f], a);
            out[n * 3 + f] = a;
        }
    }
}

// ---------------------------------------------------------------------------
extern "C" void kernel_launch(void* const* d_in, const int* in_sizes, int n_in,
                              void* d_out, int out_size) {
    const float* x    = (const float*)d_in[0];
    const float* y    = (const float*)d_in[1];
    const float* t    = (const float*)d_in[2];
    const float* W1   = (const float*)d_in[3];
    const float* b1   = (const float*)d_in[4];
    const float* wa   = (const float*)d_in[5];
    const float* wb   = (const float*)d_in[6];
    const float* W2   = (const float*)d_in[7];
    const float* b2   = (const float*)d_in[8];
    const float* mW1  = (const float*)d_in[9];
    const float* mb1  = (const float*)d_in[10];
    const float* mwa  = (const float*)d_in[11];
    const float* mwb  = (const float*)d_in[12];
    const float* mW2  = (const float*)d_in[13];
    const float* mb2  = (const float*)d_in[14];
    const float* W0   = (const float*)d_in[15];
    const float* b0   = (const float*)d_in[16];
    const float* wa0  = (const float*)d_in[17];
    const float* wb0  = (const float*)d_in[18];
    const float* Wh   = (const float*)d_in[19];
    const float* bh   = (const float*)d_in[20];
    const float* wah  = (const float*)d_in[21];
    const float* wbh  = (const float*)d_in[22];
    const float* Wf1  = (const float*)d_in[23];
    const float* bf1  = (const float*)d_in[24];
    const float* waf  = (const float*)d_in[25];
    const float* wbf  = (const float*)d_in[26];
    const float* Wf2  = (const float*)d_in[27];
    const float* bf2  = (const float*)d_in[28];
    float* out = (float*)d_out;

    int npts = in_sizes[0];
    int nblocks = (npts + PPB - 1) / PPB;

    setup_cd_kernel<<<1, 192>>>(W1);
    model_main_kernel<<<nblocks, NTHREADS>>>(
        x, y, t, W1, b1, wa, wb, W2, b2,
        mW1, mb1, mwa, mwb, mW2, mb2,
        W0, b0, wa0, wb0, Wh, bh, wah, wbh,
        Wf1, bf1, waf, wbf, Wf2, bf2,
        out, npts);
}

// round 2
// speedup vs baseline: 1.5027x; 1.5027x over previous
#include <cuda_runtime.h>

// ---------------------------------------------------------------------------
// Model_38225208935040: multi-region perturbed PINN forward.
//
// Algebraic collapse: mean over each symmetric perturbation grid of
// wave(base + delta) = Cd * wave(base), with
//   Cd_j = prod_d [ (1/s) * sum_i cos(lin_i * W1[d, j]) ]
// (sin-mean vanishes on a symmetric grid; the grid mean factorizes per dim).
// So 496 embedding evals/point -> 1 wave(base) + 3 precomputed 64-vectors.
// ---------------------------------------------------------------------------

#define PPB 4          // points per block
#define NTHREADS 256

__device__ float g_Cd[3 * 64];

// -------------------------- setup: compute Cd ------------------------------
__global__ void setup_cd_kernel(const float* __restrict__ W1) {
    int tid = threadIdx.x;
    if (tid >= 192) return;
    int r = tid >> 6;
    int j = tid & 63;
    const int   S[3] = {3, 5, 7};
    const float R[3] = {0.01f, 0.05f, 0.09f};
    int s = S[r];
    float rr = R[r];
    float inv = 1.0f / (float)s;
    float step = 2.0f * rr / (float)(s - 1);
    float prod = 1.0f;
    #pragma unroll
    for (int d = 0; d < 3; d++) {
        float w = W1[d * 64 + j];
        float c = 0.0f;
        for (int i = 0; i < s; i++) {
            float lin = -rr + step * (float)i;
            c += cosf(lin * w);
        }
        prod *= c * inv;
    }
    g_Cd[r * 64 + j] = prod;
}

// -------------------------- main fused kernel ------------------------------
__global__ void __launch_bounds__(NTHREADS) model_main_kernel(
    const float* __restrict__ x, const float* __restrict__ y, const float* __restrict__ t,
    const float* __restrict__ W1, const float* __restrict__ b1,
    const float* __restrict__ pwa, const float* __restrict__ pwb,
    const float* __restrict__ W2, const float* __restrict__ b2,
    const float* __restrict__ mW1, const float* __restrict__ mb1,
    const float* __restrict__ pmwa, const float* __restrict__ pmwb,
    const float* __restrict__ mW2, const float* __restrict__ pmb2,
    const float* __restrict__ W0, const float* __restrict__ b0,
    const float* __restrict__ pwa0, const float* __restrict__ pwb0,
    const float* __restrict__ Wh, const float* __restrict__ bh,
    const float* __restrict__ wah, const float* __restrict__ wbh,
    const float* __restrict__ Wf1, const float* __restrict__ bf1,
    const float* __restrict__ pwaf, const float* __restrict__ pwbf,
    const float* __restrict__ Wf2, const float* __restrict__ bf2,
    float* __restrict__ out, int npts)
{
    __shared__ float4 swc[PPB][64];      // (w, Cd1*w, Cd2*w, Cd3*w)
    __shared__ float  esh[PPB][256];     // mixed features e
    __shared__ float  hsh[PPB][64];      // out-MLP hidden state
    __shared__ float4 pshare[4][PPB][16];// split-K partials [group][pt][f-quad]

    const int tid = threadIdx.x;
    const int base_pt = blockIdx.x * PPB;

    // ---------------- Phase A: base embedding pre-activation ---------------
    {
        const float wa = pwa[0], wb = pwb[0];
        int pt = tid >> 6;
        int j  = tid & 63;
        int n  = base_pt + pt;
        if (n >= npts) n = npts - 1;
        float xv = x[n], yv = y[n], tv = t[n];
        float z = fmaf(xv, W1[j], fmaf(yv, W1[64 + j], fmaf(tv, W1[128 + j], b1[j])));
        float sn, cn;
        __sincosf(z, &sn, &cn);
        float w = fmaf(wa, sn, wb * cn);
        float c1 = g_Cd[j], c2 = g_Cd[64 + j], c3 = g_Cd[128 + j];
        swc[pt][j] = make_float4(w, c1 * w, c2 * w, c3 * w);
    }
    __syncthreads();

    // ---------------- Phase B: 4-region GEMV vs W2 [64,256], vectorized ----
    // Thread owns 4 consecutive output columns (quad q) for one point.
    {
        const int q   = tid & 63;        // column quad: cols 4q..4q+3
        const int ptB = tid >> 6;
        const float4* __restrict__ W2v = (const float4*)W2;   // [64][64] float4
        // a_c = (s0,s1,s2,s3) region sums for column 4q+c
        float4 a0 = {0,0,0,0}, a1 = {0,0,0,0}, a2 = {0,0,0,0}, a3 = {0,0,0,0};
        #pragma unroll
        for (int j = 0; j < 64; j++) {
            float4 c = swc[ptB][j];                 // broadcast LDS.128
            float4 w = W2v[j * 64 + q];             // coalesced LDG.128
            a0.x = fmaf(c.x, w.x, a0.x); a0.y = fmaf(c.y, w.x, a0.y);
            a0.z = fmaf(c.z, w.x, a0.z); a0.w = fmaf(c.w, w.x, a0.w);
            a1.x = fmaf(c.x, w.y, a1.x); a1.y = fmaf(c.y, w.y, a1.y);
            a1.z = fmaf(c.z, w.y, a1.z); a1.w = fmaf(c.w, w.y, a1.w);
            a2.x = fmaf(c.x, w.z, a2.x); a2.y = fmaf(c.y, w.z, a2.y);
            a2.z = fmaf(c.z, w.z, a2.z); a2.w = fmaf(c.w, w.z, a2.w);
            a3.x = fmaf(c.x, w.w, a3.x); a3.y = fmaf(c.y, w.w, a3.y);
            a3.z = fmaf(c.z, w.w, a3.z); a3.w = fmaf(c.w, w.w, a3.w);
        }

        // ------------- Phase C: multiregion mixer (4 -> 8 -> 1) ------------
        const float4 b2q = ((const float4*)b2)[q];
        const float mwa = pmwa[0], mwb = pmwb[0], mb2v = pmb2[0];
        float4 sv0 = make_float4(a0.x + b2q.x, a1.x + b2q.y, a2.x + b2q.z, a3.x + b2q.w);
        float4 sv1 = make_float4(a0.y + b2q.x, a1.y + b2q.y, a2.y + b2q.z, a3.y + b2q.w);
        float4 sv2 = make_float4(a0.z + b2q.x, a1.z + b2q.y, a2.z + b2q.z, a3.z + b2q.w);
        float4 sv3 = make_float4(a0.w + b2q.x, a1.w + b2q.y, a2.w + b2q.z, a3.w + b2q.w);
        float e0 = mb2v, e1 = mb2v, e2 = mb2v, e3 = mb2v;
        #pragma unroll
        for (int h = 0; h < 8; h++) {
            float w0 = mW1[h], w1 = mW1[8 + h], w2 = mW1[16 + h], w3 = mW1[24 + h];
            float bb = mb1[h], m2 = mW2[h];
            float z0 = fmaf(sv0.x, w0, fmaf(sv1.x, w1, fmaf(sv2.x, w2, fmaf(sv3.x, w3, bb))));
            float z1 = fmaf(sv0.y, w0, fmaf(sv1.y, w1, fmaf(sv2.y, w2, fmaf(sv3.y, w3, bb))));
            float z2 = fmaf(sv0.z, w0, fmaf(sv1.z, w1, fmaf(sv2.z, w2, fmaf(sv3.z, w3, bb))));
            float z3 = fmaf(sv0.w, w0, fmaf(sv1.w, w1, fmaf(sv2.w, w2, fmaf(sv3.w, w3, bb))));
            float sn, cn;
            __sincosf(z0, &sn, &cn); e0 = fmaf(fmaf(mwa, sn, mwb * cn), m2, e0);
            __sincosf(z1, &sn, &cn); e1 = fmaf(fmaf(mwa, sn, mwb * cn), m2, e1);
            __sincosf(z2, &sn, &cn); e2 = fmaf(fmaf(mwa, sn, mwb * cn), m2, e2);
            __sincosf(z3, &sn, &cn); e3 = fmaf(fmaf(mwa, sn, mwb * cn), m2, e3);
        }
        esh[ptB][4 * q + 0] = e0;
        esh[ptB][4 * q + 1] = e1;
        esh[ptB][4 * q + 2] = e2;
        esh[ptB][4 * q + 3] = e3;
    }
    __syncthreads();

    // ---------------- Phase D: out MLP, split-K + float4 weights -----------
    const int f4  = tid & 15;          // feature quad: features 4f4..4f4+3
    const int ptD = (tid >> 4) & 3;    // point
    const int g   = tid >> 6;          // k-group
    const int pt  = tid >> 6;          // reduce-phase point
    const int f   = tid & 63;          // reduce-phase feature
    const float* ps = (const float*)pshare;   // [4][4][64]

    // layer 0: 256 -> 64
    {
        const float4* __restrict__ W0v = (const float4*)W0;  // [256][16] float4
        float4 acc = {0,0,0,0};
        #pragma unroll
        for (int kk = 0; kk < 64; kk++) {
            int k = g * 64 + kk;
            float e  = esh[ptD][k];          // broadcast LDS
            float4 w = W0v[k * 16 + f4];     // LDG.128
            acc.x = fmaf(e, w.x, acc.x);
            acc.y = fmaf(e, w.y, acc.y);
            acc.z = fmaf(e, w.z, acc.z);
            acc.w = fmaf(e, w.w, acc.w);
        }
        pshare[g][ptD][f4] = acc;
        __syncthreads();
        float a = b0[f] + (ps[(0 * 4 + pt) * 64 + f] + ps[(1 * 4 + pt) * 64 + f])
                        + (ps[(2 * 4 + pt) * 64 + f] + ps[(3 * 4 + pt) * 64 + f]);
        float sn, cn;
        __sincosf(a, &sn, &cn);
        hsh[pt][f] = fmaf(pwa0[0], sn, pwb0[0] * cn);
        __syncthreads();
    }

    // 3 hidden layers + final hidden: 64 -> 64 with wave
    #pragma unroll 1
    for (int L = 0; L < 4; L++) {
        const float* __restrict__ Wl = (L < 3) ? (Wh + L * 4096) : Wf1;
        const float* __restrict__ bl = (L < 3) ? (bh + L * 64)   : bf1;
        const float  lwa = (L < 3) ? wah[L] : pwaf[0];
        const float  lwb = (L < 3) ? wbh[L] : pwbf[0];
        const float4* __restrict__ Wv = (const float4*)Wl;   // [64][16] float4
        float4 acc = {0,0,0,0};
        #pragma unroll
        for (int kk = 0; kk < 16; kk++) {
            int k = g * 16 + kk;
            float hv = hsh[ptD][k];
            float4 w = Wv[k * 16 + f4];
            acc.x = fmaf(hv, w.x, acc.x);
            acc.y = fmaf(hv, w.y, acc.y);
            acc.z = fmaf(hv, w.z, acc.z);
            acc.w = fmaf(hv, w.w, acc.w);
        }
        pshare[g][ptD][f4] = acc;
        __syncthreads();
        float a = bl[f] + (ps[(0 * 4 + pt) * 64 + f] + ps[(1 * 4 + pt) * 64 + f])
                        + (ps[(2 * 4 + pt) * 64 + f] + ps[(3 * 4 + pt) * 64 + f]);
        float sn, cn;
        __sincosf(a, &sn, &cn);
        float hv = fmaf(lwa, sn, lwb * cn);
        __syncthreads();
        hsh[pt][f] = hv;
        __syncthreads();
    }

    // output: 64 -> 3
    if (f < 3) {
        int n = base_pt + pt;
        if (n < npts) {
            float a0 = 0.f, a1 = 0.f, a2 = 0.f, a3 = 0.f;
            #pragma unroll
            for (int i = 0; i < 16; i++) {
                a0 = fmaf(hsh[pt][4 * i + 0], Wf2[(4 * i + 0) * 3 + f], a0);
                a1 = fmaf(hsh[pt][4 * i + 1], Wf2[(4 * i + 1) * 3 + f], a1);
                a2 = fmaf(hsh[pt][4 * i + 2], Wf2[(4 * i + 2) * 3 + f], a2);
                a3 = fmaf(hsh[pt][4 * i + 3], Wf2[(4 * i + 3) * 3 + f], a3);
            }
            out[n * 3 + f] = bf2[f] + (a0 + a1) + (a2 + a3);
        }
    }
}

// ---------------------------------------------------------------------------
extern "C" void kernel_launch(void* const* d_in, const int* in_sizes, int n_in,
                              void* d_out, int out_size) {
    const float* x    = (const float*)d_in[0];
    const float* y    = (const float*)d_in[1];
    const float* t    = (const float*)d_in[2];
    const float* W1   = (const float*)d_in[3];
    const float* b1   = (const float*)d_in[4];
    const float* wa   = (const float*)d_in[5];
    const float* wb   = (const float*)d_in[6];
    const float* W2   = (const float*)d_in[7];
    const float* b2   = (const float*)d_in[8];
    const float* mW1  = (const float*)d_in[9];
    const float* mb1  = (const float*)d_in[10];
    const float* mwa  = (const float*)d_in[11];
    const float* mwb  = (const float*)d_in[12];
    const float* mW2  = (const float*)d_in[13];
    const float* mb2  = (const float*)d_in[14];
    const float* W0   = (const float*)d_in[15];
    const float* b0   = (const float*)d_in[16];
    const float* wa0  = (const float*)d_in[17];
    const float* wb0  = (const float*)d_in[18];
    const float* Wh   = (const float*)d_in[19];
    const float* bh   = (const float*)d_in[20];
    const float* wah  = (const float*)d_in[21];
    const float* wbh  = (const float*)d_in[22];
    const float* Wf1  = (const float*)d_in[23];
    const float* bf1  = (const float*)d_in[24];
    const float* waf  = (const float*)d_in[25];
    const float* wbf  = (const float*)d_in[26];
    const float* Wf2  = (const float*)d_in[27];
    const float* bf2  = (const float*)d_in[28];
    float* out = (float*)d_out;

    int npts = in_sizes[0];
    int nblocks = (npts + PPB - 1) / PPB;

    setup_cd_kernel<<<1, 192>>>(W1);
    model_main_kernel<<<nblocks, NTHREADS>>>(
        x, y, t, W1, b1, wa, wb, W2, b2,
        mW1, mb1, mwa, mwb, mW2, mb2,
        W0, b0, wa0, wb0, Wh, bh, wah, wbh,
        Wf1, bf1, waf, wbf, Wf2, bf2,
        out, npts);
}

// round 3
// speedup vs baseline: 1.9101x; 1.2711x over previous
#include <cuda_runtime.h>

// ---------------------------------------------------------------------------
// Model_38225208935040: multi-region perturbed PINN forward.
//
// Algebraic collapse: mean over each symmetric perturbation grid of
// wave(base + delta) = Cd * wave(base), with
//   Cd_j = prod_d [ (1/s) * sum_i cos(lin_i * W1[d, j]) ]
// So 496 embedding evals/point -> 1 wave(base) + 3 precomputed 64-vectors.
//
// R3: 8 points/block, 2 points/thread in the GEMV phases so every weight
// float4 fetched from L1 feeds 2x the FMAs (kernel was L1-bound at 51%).
// ---------------------------------------------------------------------------

#define PPB 8          // points per block
#define NTHREADS 256
#define EPAD 260       // esh row stride (bank-conflict padding)
#define HPAD 68        // hsh row stride

__device__ float g_Cd[3 * 64];

// -------------------------- setup: compute Cd ------------------------------
__global__ void setup_cd_kernel(const float* __restrict__ W1) {
    int tid = threadIdx.x;
    if (tid >= 192) return;
    int r = tid >> 6;
    int j = tid & 63;
    const int   S[3] = {3, 5, 7};
    const float R[3] = {0.01f, 0.05f, 0.09f};
    int s = S[r];
    float rr = R[r];
    float inv = 1.0f / (float)s;
    float step = 2.0f * rr / (float)(s - 1);
    float prod = 1.0f;
    #pragma unroll
    for (int d = 0; d < 3; d++) {
        float w = W1[d * 64 + j];
        float c = 0.0f;
        for (int i = 0; i < s; i++) {
            float lin = -rr + step * (float)i;
            c += cosf(lin * w);
        }
        prod *= c * inv;
    }
    g_Cd[r * 64 + j] = prod;
}

// -------------------------- main fused kernel ------------------------------
__global__ void __launch_bounds__(NTHREADS) model_main_kernel(
    const float* __restrict__ x, const float* __restrict__ y, const float* __restrict__ t,
    const float* __restrict__ W1, const float* __restrict__ b1,
    const float* __restrict__ pwa, const float* __restrict__ pwb,
    const float* __restrict__ W2, const float* __restrict__ b2,
    const float* __restrict__ mW1, const float* __restrict__ mb1,
    const float* __restrict__ pmwa, const float* __restrict__ pmwb,
    const float* __restrict__ mW2, const float* __restrict__ pmb2,
    const float* __restrict__ W0, const float* __restrict__ b0,
    const float* __restrict__ pwa0, const float* __restrict__ pwb0,
    const float* __restrict__ Wh, const float* __restrict__ bh,
    const float* __restrict__ wah, const float* __restrict__ wbh,
    const float* __restrict__ Wf1, const float* __restrict__ bf1,
    const float* __restrict__ pwaf, const float* __restrict__ pwbf,
    const float* __restrict__ Wf2, const float* __restrict__ bf2,
    float* __restrict__ out, int npts)
{
    __shared__ float4 swc[PPB][64];        // (w, Cd1*w, Cd2*w, Cd3*w)
    __shared__ float  esh[PPB][EPAD];      // mixed features e (padded rows)
    __shared__ float  hsh[PPB][HPAD];      // out-MLP hidden state (padded)
    __shared__ float4 pshare[4][PPB][16];  // split-K partials [group][pt][f-quad]

    const int tid = threadIdx.x;
    const int base_pt = blockIdx.x * PPB;

    // ---------------- Phase A: base embedding pre-activation ---------------
    {
        const float wa = pwa[0], wb = pwb[0];
        #pragma unroll
        for (int it = 0; it < 2; it++) {
            int i  = tid + it * NTHREADS;
            int pt = i >> 6;
            int j  = i & 63;
            int n  = base_pt + pt;
            if (n >= npts) n = npts - 1;
            float xv = x[n], yv = y[n], tv = t[n];
            float z = fmaf(xv, W1[j], fmaf(yv, W1[64 + j], fmaf(tv, W1[128 + j], b1[j])));
            float sn, cn;
            __sincosf(z, &sn, &cn);
            float w = fmaf(wa, sn, wb * cn);
            float c1 = g_Cd[j], c2 = g_Cd[64 + j], c3 = g_Cd[128 + j];
            swc[pt][j] = make_float4(w, c1 * w, c2 * w, c3 * w);
        }
    }
    __syncthreads();

    // ---------------- Phase B: 4-region GEMV vs W2 [64,256] ----------------
    // Thread owns column quad q for TWO points (pg and pg+4); each weight
    // float4 load feeds 32 FMAs.
    {
        const int q  = tid & 63;
        const int pg = tid >> 6;             // points pg and pg+4 (warp-uniform)
        const float4* __restrict__ W2v = (const float4*)W2;   // [64][64] float4
        float4 a[2][4];                      // [pt][col] -> 4 region sums
        #pragma unroll
        for (int p = 0; p < 2; p++)
            #pragma unroll
            for (int c = 0; c < 4; c++)
                a[p][c] = make_float4(0.f, 0.f, 0.f, 0.f);

        #pragma unroll 8
        for (int j = 0; j < 64; j++) {
            float4 w  = W2v[j * 64 + q];     // coalesced LDG.128
            float4 c0 = swc[pg][j];          // broadcast LDS.128
            float4 c1 = swc[pg + 4][j];
            a[0][0].x = fmaf(c0.x, w.x, a[0][0].x); a[0][0].y = fmaf(c0.y, w.x, a[0][0].y);
            a[0][0].z = fmaf(c0.z, w.x, a[0][0].z); a[0][0].w = fmaf(c0.w, w.x, a[0][0].w);
            a[0][1].x = fmaf(c0.x, w.y, a[0][1].x); a[0][1].y = fmaf(c0.y, w.y, a[0][1].y);
            a[0][1].z = fmaf(c0.z, w.y, a[0][1].z); a[0][1].w = fmaf(c0.w, w.y, a[0][1].w);
            a[0][2].x = fmaf(c0.x, w.z, a[0][2].x); a[0][2].y = fmaf(c0.y, w.z, a[0][2].y);
            a[0][2].z = fmaf(c0.z, w.z, a[0][2].z); a[0][2].w = fmaf(c0.w, w.z, a[0][2].w);
            a[0][3].x = fmaf(c0.x, w.w, a[0][3].x); a[0][3].y = fmaf(c0.y, w.w, a[0][3].y);
            a[0][3].z = fmaf(c0.z, w.w, a[0][3].z); a[0][3].w = fmaf(c0.w, w.w, a[0][3].w);
            a[1][0].x = fmaf(c1.x, w.x, a[1][0].x); a[1][0].y = fmaf(c1.y, w.x, a[1][0].y);
            a[1][0].z = fmaf(c1.z, w.x, a[1][0].z); a[1][0].w = fmaf(c1.w, w.x, a[1][0].w);
            a[1][1].x = fmaf(c1.x, w.y, a[1][1].x); a[1][1].y = fmaf(c1.y, w.y, a[1][1].y);
            a[1][1].z = fmaf(c1.z, w.y, a[1][1].z); a[1][1].w = fmaf(c1.w, w.y, a[1][1].w);
            a[1][2].x = fmaf(c1.x, w.z, a[1][2].x); a[1][2].y = fmaf(c1.y, w.z, a[1][2].y);
            a[1][2].z = fmaf(c1.z, w.z, a[1][2].z); a[1][2].w = fmaf(c1.w, w.z, a[1][2].w);
            a[1][3].x = fmaf(c1.x, w.w, a[1][3].x); a[1][3].y = fmaf(c1.y, w.w, a[1][3].y);
            a[1][3].z = fmaf(c1.z, w.w, a[1][3].z); a[1][3].w = fmaf(c1.w, w.w, a[1][3].w);
        }

        // ------------- Phase C: multiregion mixer (4 -> 8 -> 1) ------------
        const float4 b2q = ((const float4*)b2)[q];
        const float mwa = pmwa[0], mwb = pmwb[0], mb2v = pmb2[0];
        #pragma unroll
        for (int p = 0; p < 2; p++) {
            int ptc = pg + 4 * p;
            // sv[c] = region sums for column 4q+c (region r in component r)
            float4 sv0 = make_float4(a[p][0].x + b2q.x, a[p][1].x + b2q.y,
                                     a[p][2].x + b2q.z, a[p][3].x + b2q.w);
            float4 sv1 = make_float4(a[p][0].y + b2q.x, a[p][1].y + b2q.y,
                                     a[p][2].y + b2q.z, a[p][3].y + b2q.w);
            float4 sv2 = make_float4(a[p][0].z + b2q.x, a[p][1].z + b2q.y,
                                     a[p][2].z + b2q.z, a[p][3].z + b2q.w);
            float4 sv3 = make_float4(a[p][0].w + b2q.x, a[p][1].w + b2q.y,
                                     a[p][2].w + b2q.z, a[p][3].w + b2q.w);
            float e0 = mb2v, e1 = mb2v, e2 = mb2v, e3 = mb2v;
            #pragma unroll
            for (int h = 0; h < 8; h++) {
                float w0 = mW1[h], w1 = mW1[8 + h], w2 = mW1[16 + h], w3 = mW1[24 + h];
                float bb = mb1[h], m2 = mW2[h];
                float z0 = fmaf(sv0.x, w0, fmaf(sv1.x, w1, fmaf(sv2.x, w2, fmaf(sv3.x, w3, bb))));
                float z1 = fmaf(sv0.y, w0, fmaf(sv1.y, w1, fmaf(sv2.y, w2, fmaf(sv3.y, w3, bb))));
                float z2 = fmaf(sv0.z, w0, fmaf(sv1.z, w1, fmaf(sv2.z, w2, fmaf(sv3.z, w3, bb))));
                float z3 = fmaf(sv0.w, w0, fmaf(sv1.w, w1, fmaf(sv2.w, w2, fmaf(sv3.w, w3, bb))));
                float sn, cn;
                __sincosf(z0, &sn, &cn); e0 = fmaf(fmaf(mwa, sn, mwb * cn), m2, e0);
                __sincosf(z1, &sn, &cn); e1 = fmaf(fmaf(mwa, sn, mwb * cn), m2, e1);
                __sincosf(z2, &sn, &cn); e2 = fmaf(fmaf(mwa, sn, mwb * cn), m2, e2);
                __sincosf(z3, &sn, &cn); e3 = fmaf(fmaf(mwa, sn, mwb * cn), m2, e3);
            }
            esh[ptc][4 * q + 0] = e0;
            esh[ptc][4 * q + 1] = e1;
            esh[ptc][4 * q + 2] = e2;
            esh[ptc][4 * q + 3] = e3;
        }
    }
    __syncthreads();

    // ---------------- Phase D: out MLP, split-K + 2 pts/thread -------------
    const int f4 = tid & 15;           // feature quad
    const int pp = (tid >> 4) & 3;     // points pp and pp+4
    const int g  = tid >> 6;           // k-group
    const float* ps = (const float*)pshare;   // flat [g][pt][64]

    // layer 0: 256 -> 64 (k split 4 x 64)
    {
        const float4* __restrict__ W0v = (const float4*)W0;  // [256][16] float4
        float4 acc0 = {0,0,0,0}, acc1 = {0,0,0,0};
        #pragma unroll 8
        for (int kk = 0; kk < 64; kk++) {
            int k = g * 64 + kk;
            float4 w = W0v[k * 16 + f4];
            float e0 = esh[pp][k];
            float e1 = esh[pp + 4][k];
            acc0.x = fmaf(e0, w.x, acc0.x); acc0.y = fmaf(e0, w.y, acc0.y);
            acc0.z = fmaf(e0, w.z, acc0.z); acc0.w = fmaf(e0, w.w, acc0.w);
            acc1.x = fmaf(e1, w.x, acc1.x); acc1.y = fmaf(e1, w.y, acc1.y);
            acc1.z = fmaf(e1, w.z, acc1.z); acc1.w = fmaf(e1, w.w, acc1.w);
        }
        pshare[g][pp][f4]     = acc0;
        pshare[g][pp + 4][f4] = acc1;
        __syncthreads();
        const float lwa = pwa0[0], lwb = pwb0[0];
        #pragma unroll
        for (int it = 0; it < 2; it++) {
            int i = tid + it * NTHREADS;
            int ptR = i >> 6, f = i & 63;
            float a = b0[f] + (ps[(0 * PPB + ptR) * 64 + f] + ps[(1 * PPB + ptR) * 64 + f])
                            + (ps[(2 * PPB + ptR) * 64 + f] + ps[(3 * PPB + ptR) * 64 + f]);
            float sn, cn;
            __sincosf(a, &sn, &cn);
            hsh[ptR][f] = fmaf(lwa, sn, lwb * cn);
        }
        __syncthreads();
    }

    // 3 hidden layers + final hidden: 64 -> 64 with wave (k split 4 x 16)
    #pragma unroll 1
    for (int L = 0; L < 4; L++) {
        const float* __restrict__ Wl = (L < 3) ? (Wh + L * 4096) : Wf1;
        const float* __restrict__ bl = (L < 3) ? (bh + L * 64)   : bf1;
        const float  lwa = (L < 3) ? wah[L] : pwaf[0];
        const float  lwb = (L < 3) ? wbh[L] : pwbf[0];
        const float4* __restrict__ Wv = (const float4*)Wl;   // [64][16] float4
        float4 acc0 = {0,0,0,0}, acc1 = {0,0,0,0};
        #pragma unroll
        for (int kk = 0; kk < 16; kk++) {
            int k = g * 16 + kk;
            float4 w = Wv[k * 16 + f4];
            float h0 = hsh[pp][k];
            float h1 = hsh[pp + 4][k];
            acc0.x = fmaf(h0, w.x, acc0.x); acc0.y = fmaf(h0, w.y, acc0.y);
            acc0.z = fmaf(h0, w.z, acc0.z); acc0.w = fmaf(h0, w.w, acc0.w);
            acc1.x = fmaf(h1, w.x, acc1.x); acc1.y = fmaf(h1, w.y, acc1.y);
            acc1.z = fmaf(h1, w.z, acc1.z); acc1.w = fmaf(h1, w.w, acc1.w);
        }
        pshare[g][pp][f4]     = acc0;
        pshare[g][pp + 4][f4] = acc1;
        __syncthreads();
        #pragma unroll
        for (int it = 0; it < 2; it++) {
            int i = tid + it * NTHREADS;
            int ptR = i >> 6, f = i & 63;
            float a = bl[f] + (ps[(0 * PPB + ptR) * 64 + f] + ps[(1 * PPB + ptR) * 64 + f])
                            + (ps[(2 * PPB + ptR) * 64 + f] + ps[(3 * PPB + ptR) * 64 + f]);
            float sn, cn;
            __sincosf(a, &sn, &cn);
            float hv = fmaf(lwa, sn, lwb * cn);
            // safe to write: all reads of hsh for this layer completed before
            // the barrier above only if we sync again; use two-phase write.
            pshare[0][0][0].x = pshare[0][0][0].x;  // no-op
            __syncthreads();
            hsh[ptR][f] = hv;
        }
        __syncthreads();
    }

    // output: 64 -> 3
    if (tid < PPB * 3) {
        int pt = tid / 3, f = tid % 3;
        int n = base_pt + pt;
        if (n < npts) {
            float a0 = 0.f, a1 = 0.f, a2 = 0.f, a3 = 0.f;
            #pragma unroll
            for (int i = 0; i < 16; i++) {
                a0 = fmaf(hsh[pt][4 * i + 0], Wf2[(4 * i + 0) * 3 + f], a0);
                a1 = fmaf(hsh[pt][4 * i + 1], Wf2[(4 * i + 1) * 3 + f], a1);
                a2 = fmaf(hsh[pt][4 * i + 2], Wf2[(4 * i + 2) * 3 + f], a2);
                a3 = fmaf(hsh[pt][4 * i + 3], Wf2[(4 * i + 3) * 3 + f], a3);
            }
            out[n * 3 + f] = bf2[f] + (a0 + a1) + (a2 + a3);
        }
    }
}

// ---------------------------------------------------------------------------
extern "C" void kernel_launch(void* const* d_in, const int* in_sizes, int n_in,
                              void* d_out, int out_size) {
    const float* x    = (const float*)d_in[0];
    const float* y    = (const float*)d_in[1];
    const float* t    = (const float*)d_in[2];
    const float* W1   = (const float*)d_in[3];
    const float* b1   = (const float*)d_in[4];
    const float* wa   = (const float*)d_in[5];
    const float* wb   = (const float*)d_in[6];
    const float* W2   = (const float*)d_in[7];
    const float* b2   = (const float*)d_in[8];
    const float* mW1  = (const float*)d_in[9];
    const float* mb1  = (const float*)d_in[10];
    const float* mwa  = (const float*)d_in[11];
    const float* mwb  = (const float*)d_in[12];
    const float* mW2  = (const float*)d_in[13];
    const float* mb2  = (const float*)d_in[14];
    const float* W0   = (const float*)d_in[15];
    const float* b0   = (const float*)d_in[16];
    const float* wa0  = (const float*)d_in[17];
    const float* wb0  = (const float*)d_in[18];
    const float* Wh   = (const float*)d_in[19];
    const float* bh   = (const float*)d_in[20];
    const float* wah  = (const float*)d_in[21];
    const float* wbh  = (const float*)d_in[22];
    const float* Wf1  = (const float*)d_in[23];
    const float* bf1  = (const float*)d_in[24];
    const float* waf  = (const float*)d_in[25];
    const float* wbf  = (const float*)d_in[26];
    const float* Wf2  = (const float*)d_in[27];
    const float* bf2  = (const float*)d_in[28];
    float* out = (float*)d_out;

    int npts = in_sizes[0];
    int nblocks = (npts + PPB - 1) / PPB;

    setup_cd_kernel<<<1, 192>>>(W1);
    model_main_kernel<<<nblocks, NTHREADS>>>(
        x, y, t, W1, b1, wa, wb, W2, b2,
        mW1, mb1, mwa, mwb, mW2, mb2,
        W0, b0, wa0, wb0, Wh, bh, wah, wbh,
        Wf1, bf1, waf, wbf, Wf2, bf2,
        out, npts);
}